// round 2
// baseline (speedup 1.0000x reference)
#include <cuda_runtime.h>

#define HW 128
#define CC 64
#define BBATCH 32
#define KK 1000
#define LL 12
#define OO 24

// Intermediate activation h in NHWC layout: [B][H][W][C]  (128 MB scratch)
__device__ float g_h[BBATCH * HW * HW * CC];

// ---------- packed f32x2 helpers (Blackwell FFMA2) ----------
__device__ __forceinline__ unsigned long long ffma2(unsigned long long a,
                                                    unsigned long long b,
                                                    unsigned long long c) {
    unsigned long long d;
    asm("fma.rn.f32x2 %0, %1, %2, %3;" : "=l"(d) : "l"(a), "l"(b), "l"(c));
    return d;
}
__device__ __forceinline__ unsigned long long pack2(float lo, float hi) {
    unsigned long long d;
    asm("mov.b64 %0, {%1, %2};" : "=l"(d) : "f"(lo), "f"(hi));
    return d;
}
__device__ __forceinline__ void unpack2(unsigned long long v, float& lo, float& hi) {
    asm("mov.b64 {%0, %1}, %2;" : "=f"(lo), "=f"(hi) : "l"(v));
}

// ============================================================================
// Kernel A: 3x3 conv (pad 1) + bias + LeakyReLU(0.02), NCHW in -> NHWC out.
// One block per (row y, image b). 256 threads:
//   tx = t&31  -> 4 pixels (px = tx*4 + i)
//   ty = t>>5  -> 8 output channels (co = ty*8 .. +7), held as 4 f32x2 pairs
// c_in processed in chunks of 8 through shared memory.
// ============================================================================
__global__ __launch_bounds__(256) void conv_lrelu_kernel(
    const float* __restrict__ x,      // [B][C][H][W]
    const float* __restrict__ w,      // [Cout][Cin][3][3]
    const float* __restrict__ bias)   // [Cout]
{
    // xs: 8 ci x 3 dy x 136 (4-word left pad so float4 reads stay 16B aligned;
    //     data at [4..131], zero pads at [3] and [132])
    __shared__ float xs[8 * 3 * 136];          // 13,056 B
    // ws: [rem=ci*9+dy*3+dx (72)][co (64)] with stride 66 to dodge store conflicts;
    //     adjacent co pairs read as float2 (broadcast across the warp).
    __shared__ float ws[72 * 66];              // 19,008 B

    const int y = blockIdx.x;
    const int b = blockIdx.y;
    const int t = threadIdx.x;
    const int tx = t & 31;
    const int ty = t >> 5;

    unsigned long long acc2[4][4];
#pragma unroll
    for (int cp = 0; cp < 4; cp++)
#pragma unroll
        for (int i = 0; i < 4; i++) acc2[cp][i] = 0ULL;

    for (int chunk = 0; chunk < 8; ++chunk) {
        const int ci0 = chunk * 8;

        // ---- stage input rows (y-1, y, y+1) for 8 input channels ----
        for (int i = t; i < 8 * 3 * 128; i += 256) {
            int ci = i / 384;
            int r  = i - ci * 384;
            int dy = r >> 7;
            int px = r & 127;
            int row = y + dy - 1;
            float v = 0.f;
            if ((unsigned)row < 128u)
                v = x[(((b * CC + ci0 + ci) * HW + row) << 7) + px];
            xs[(ci * 3 + dy) * 136 + 4 + px] = v;
        }
        if (t < 48) {  // zero the horizontal halo pads
            int ci = t / 6; int r = t - ci * 6; int dy = r >> 1; int side = r & 1;
            xs[(ci * 3 + dy) * 136 + (side ? 132 : 3)] = 0.f;
        }

        // ---- stage weights for this ci chunk: 64 co x 8 ci x 9 taps ----
        for (int i = t; i < 4608; i += 256) {
            int co  = i / 72;
            int rem = i - co * 72;             // rem = ci*9 + dy*3 + dx
            ws[rem * 66 + co] = w[co * 576 + ci0 * 9 + rem];
        }
        __syncthreads();

        // ---- main FMA loop ----
#pragma unroll
        for (int ci = 0; ci < 8; ++ci) {
#pragma unroll
            for (int dy = 0; dy < 3; ++dy) {
                const float* xr = &xs[(ci * 3 + dy) * 136];
                float4 V = *reinterpret_cast<const float4*>(xr + 4 + tx * 4);
                float v0 = xr[3 + tx * 4];
                float v5 = xr[8 + tx * 4];
                unsigned long long bb[6];
                bb[0] = pack2(v0, v0);  bb[1] = pack2(V.x, V.x);
                bb[2] = pack2(V.y, V.y); bb[3] = pack2(V.z, V.z);
                bb[4] = pack2(V.w, V.w); bb[5] = pack2(v5, v5);
#pragma unroll
                for (int dx = 0; dx < 3; ++dx) {
                    const float2* wrow =
                        reinterpret_cast<const float2*>(&ws[(ci * 9 + dy * 3 + dx) * 66]);
#pragma unroll
                    for (int cp = 0; cp < 4; ++cp) {
                        float2 wp = wrow[ty * 4 + cp];
                        unsigned long long wpp = pack2(wp.x, wp.y);
#pragma unroll
                        for (int i = 0; i < 4; i++)
                            acc2[cp][i] = ffma2(wpp, bb[dx + i], acc2[cp][i]);
                    }
                }
            }
        }
        __syncthreads();
    }

    // ---- epilogue: bias + leaky relu, store NHWC ----
    float* hb = &g_h[((b * HW + y) * HW) * CC];
#pragma unroll
    for (int cp = 0; cp < 4; ++cp) {
        int co = ty * 8 + cp * 2;
        float b0 = bias[co], b1 = bias[co + 1];
#pragma unroll
        for (int i = 0; i < 4; i++) {
            float a0, a1;
            unpack2(acc2[cp][i], a0, a1);
            a0 += b0; a1 += b1;
            a0 = a0 > 0.f ? a0 : 0.02f * a0;
            a1 = a1 > 0.f ? a1 : 0.02f * a1;
            int px = tx * 4 + i;
            *reinterpret_cast<float2*>(&hb[px * CC + co]) = make_float2(a0, a1);
        }
    }
}

// ============================================================================
// Kernel B: gather 12 positions x 64ch from NHWC h, multiply by pred_w^T (24x768).
// One warp per (k,b) pair; pred_w staged through smem in two 36 KB halves.
// out[(k*32+b)*24 + o], matching reference transpose(1,0,2).
// ============================================================================
__global__ __launch_bounds__(256) void gather_fc_kernel(
    const int* __restrict__ pos,     // [K][B][L][2] (x, y)
    const float* __restrict__ pw,    // [24][768]
    const float* __restrict__ pb,    // [24]
    float* __restrict__ out)         // [K][B][24]
{
    __shared__ float wsm[OO * 384];  // 36,864 B: half of pred_w

    const int t = threadIdx.x;
    const int lane = t & 31;
    const int warp = t >> 5;
    const int pair = blockIdx.x * 8 + warp;   // pair = k*32 + b, grid covers exactly 32000
    const int k = pair >> 5;
    const int b = pair & 31;

    float acc[OO];
#pragma unroll
    for (int o = 0; o < OO; o++) acc[o] = 0.f;

    const float* __restrict__ h = g_h;

    for (int half = 0; half < 2; ++half) {
        __syncthreads();
        for (int i = t * 4; i < OO * 384; i += 1024) {
            int o = i / 384;
            int j = i - o * 384;
            *reinterpret_cast<float4*>(&wsm[i]) =
                *reinterpret_cast<const float4*>(&pw[o * 768 + half * 384 + j]);
        }
        __syncthreads();

#pragma unroll
        for (int j24 = 0; j24 < 12; ++j24) {
            int j24g = half * 12 + j24;
            int l = j24g >> 1;
            const int* pp = &pos[((k * BBATCH + b) * LL + l) * 2];
            int px = pp[0];
            int py = pp[1];
            px = px < 0 ? 0 : (px > 127 ? 127 : px);
            py = py < 0 ? 0 : (py > 127 ? 127 : py);
            int c = lane + ((j24g & 1) << 5);
            float hv = h[(((b * HW + py) * HW) + px) * CC + c];
            const float* wc = &wsm[j24 * 32 + lane];
#pragma unroll
            for (int o = 0; o < OO; o++)
                acc[o] += hv * wc[o * 384];
        }
    }

    // warp reduction over the 32 j-lanes
#pragma unroll
    for (int o = 0; o < OO; o++) {
        acc[o] += __shfl_xor_sync(0xffffffffu, acc[o], 16);
        acc[o] += __shfl_xor_sync(0xffffffffu, acc[o], 8);
        acc[o] += __shfl_xor_sync(0xffffffffu, acc[o], 4);
        acc[o] += __shfl_xor_sync(0xffffffffu, acc[o], 2);
        acc[o] += __shfl_xor_sync(0xffffffffu, acc[o], 1);
    }

    if (lane == 0) {
        float* op = &out[pair * OO];
#pragma unroll
        for (int o = 0; o < OO; o++) op[o] = acc[o] + pb[o];
    }
}

// ============================================================================
extern "C" void kernel_launch(void* const* d_in, const int* in_sizes, int n_in,
                              void* d_out, int out_size) {
    const float* x   = (const float*)d_in[0];   // [32][64][128][128]
    const int*   pos = (const int*)  d_in[1];   // [1000][32][12][2]
    const float* cw  = (const float*)d_in[2];   // [64][64][3][3]
    const float* cb  = (const float*)d_in[3];   // [64]
    const float* pw  = (const float*)d_in[4];   // [24][768]
    const float* pb  = (const float*)d_in[5];   // [24]
    float* out = (float*)d_out;                 // [1000][32][24]

    conv_lrelu_kernel<<<dim3(HW, BBATCH), 256>>>(x, cw, cb);
    gather_fc_kernel<<<(KK * BBATCH) / 8, 256>>>(pos, pw, pb, out);
}

// round 5
// speedup vs baseline: 1.4726x; 1.4726x over previous
#include <cuda_runtime.h>
#include <cuda_bf16.h>
#include <cstdint>

#define HW 128
#define CC 64
#define BBATCH 32
#define KK 1000
#define LL 12
#define OO 24

// h activations, NHWC fp32: [B][H][W][C] = 128 MB
__device__ float g_h[BBATCH * HW * HW * CC];
// pre-split bf16 weights, padded rows: [tap(9)][split(2)][co(64)][144 B] (72 bf16 slots, 64 used)
__device__ unsigned char g_wt[18 * 9216];

// ===================== small helpers =====================
__device__ __forceinline__ uint32_t smem_u32(const void* p) {
    uint32_t a;
    asm("{ .reg .u64 t; cvta.to.shared.u64 t, %1; cvt.u32.u64 %0, t; }" : "=r"(a) : "l"(p));
    return a;
}
__device__ __forceinline__ unsigned long long ffma2(unsigned long long a,
                                                    unsigned long long b,
                                                    unsigned long long c) {
    unsigned long long d;
    asm("fma.rn.f32x2 %0, %1, %2, %3;" : "=l"(d) : "l"(a), "l"(b), "l"(c));
    return d;
}
__device__ __forceinline__ unsigned long long addf2(unsigned long long a, unsigned long long b) {
    unsigned long long d;
    asm("add.rn.f32x2 %0, %1, %2;" : "=l"(d) : "l"(a), "l"(b));
    return d;
}
__device__ __forceinline__ unsigned long long pack2(float lo, float hi) {
    unsigned long long d;
    asm("mov.b64 %0, {%1, %2};" : "=l"(d) : "f"(lo), "f"(hi));
    return d;
}
__device__ __forceinline__ void unpack2(unsigned long long v, float& lo, float& hi) {
    asm("mov.b64 {%0, %1}, %2;" : "=f"(lo), "=f"(hi) : "l"(v));
}
__device__ __forceinline__ void ldsm4(uint32_t* r, uint32_t a) {
    asm volatile("ldmatrix.sync.aligned.m8n8.x4.shared.b16 {%0,%1,%2,%3}, [%4];"
                 : "=r"(r[0]), "=r"(r[1]), "=r"(r[2]), "=r"(r[3]) : "r"(a));
}
__device__ __forceinline__ void mma16816(float* d, const uint32_t* a, uint32_t b0, uint32_t b1) {
    asm volatile("mma.sync.aligned.m16n8k16.row.col.f32.bf16.bf16.f32 "
                 "{%0,%1,%2,%3}, {%4,%5,%6,%7}, {%8,%9}, {%0,%1,%2,%3};"
                 : "+f"(d[0]), "+f"(d[1]), "+f"(d[2]), "+f"(d[3])
                 : "r"(a[0]), "r"(a[1]), "r"(a[2]), "r"(a[3]), "r"(b0), "r"(b1));
}

// ===================== conv smem layout (dynamic) =====================
#define ASTRIDE 144
#define ATILE (130 * 144)        // 18,720 B per (input-row slab, split)
#define BTILE (64 * 144)         // 9,216 B per (tap, split)
#define SM_B 0                   // 6 tiles for current dy: 55,296 B
#define SM_A 55296               // 8 slabs (4 rows x hi/lo): 149,760 B
#define SM_BIAS 205056           // 64 floats
#define SM_TOT 205312

// ============================================================================
// Prep: split conv_w into bf16 hi/lo, write padded [n=co][k=ci] tiles.
// ============================================================================
__global__ void wprep_kernel(const float* __restrict__ w) {
    int idx = blockIdx.x * 256 + threadIdx.x;
    if (idx >= CC * CC * 9) return;
    int co = idx / 576;
    int rem = idx - co * 576;
    int ci = rem / 9;
    int tap = rem - ci * 9;                 // dy*3 + dx
    float f = w[idx];
    __nv_bfloat16 hb = __float2bfloat16(f);
    __nv_bfloat16 lb = __float2bfloat16(f - __bfloat162float(hb));
    *reinterpret_cast<__nv_bfloat16*>(g_wt + (tap * 2 + 0) * BTILE + co * ASTRIDE + ci * 2) = hb;
    *reinterpret_cast<__nv_bfloat16*>(g_wt + (tap * 2 + 1) * BTILE + co * ASTRIDE + ci * 2) = lb;
}

// ============================================================================
// Conv via mma.sync bf16 (3-product fp32 split). CTA = (2 rows, image b).
// 8 warps; warp w: orow = w>>2, px base (w&3)*32, two m16 tiles.
// ============================================================================
__global__ __launch_bounds__(256, 1) void conv_tc_kernel(
    const float* __restrict__ x,     // [B][C][H][W]
    const float* __restrict__ bias)  // [C]
{
    extern __shared__ unsigned char smem[];
    const uint32_t sb = smem_u32(smem);
    const int t = threadIdx.x;
    const int lane = t & 31;
    const int w = t >> 5;
    const int y0 = blockIdx.x * 2;
    const int b = blockIdx.y;
    const int orow = w >> 2;
    const int pxl = (w & 3) * 32;

    // bias
    if (t < 64) *reinterpret_cast<float*>(smem + SM_BIAS + t * 4) = bias[t];

    // zero horizontal halo rows (px=-1 and px=128) of all 8 A slabs
    for (int i = t; i < 8 * 128; i += 256) {
        int slab = i >> 7;
        int rem = i & 127;
        int row = (rem >> 6) ? 129 : 0;
        int ci = rem & 63;
        *reinterpret_cast<uint16_t*>(smem + SM_A + slab * ATILE + row * ASTRIDE + ci * 2) = 0;
    }

    // stage A: 4 input rows (y0-1 .. y0+2) -> [px][ci] bf16 hi/lo slabs
    for (int i = t; i < 4 * CC * HW; i += 256) {
        int px = i & 127;
        int ci = (i >> 7) & 63;
        int r = i >> 13;
        int yin = y0 - 1 + r;
        float f = 0.f;
        if ((unsigned)yin < 128u)
            f = x[((size_t)(b * CC + ci) * HW + yin) * HW + px];
        __nv_bfloat16 hb = __float2bfloat16(f);
        __nv_bfloat16 lb = __float2bfloat16(f - __bfloat162float(hb));
        unsigned char* p = smem + SM_A + (r * 2) * ATILE + (px + 1) * ASTRIDE + ci * 2;
        *reinterpret_cast<__nv_bfloat16*>(p) = hb;
        *reinterpret_cast<__nv_bfloat16*>(p + ATILE) = lb;
    }

    // per-lane ldmatrix address components
    const uint32_t aLaneOff = (uint32_t)((lane & 15) * ASTRIDE + (lane >> 4) * 16);
    const uint32_t bLaneOff = (uint32_t)((((lane & 7) + ((lane >> 4) << 3)) * ASTRIDE) +
                                         ((lane >> 3) & 1) * 16);

    float acc[2][8][4];
#pragma unroll
    for (int mt = 0; mt < 2; ++mt)
#pragma unroll
        for (int nt = 0; nt < 8; ++nt)
#pragma unroll
            for (int q = 0; q < 4; ++q) acc[mt][nt][q] = 0.f;

    for (int dy = 0; dy < 3; ++dy) {
        __syncthreads();
        {   // stage 6 weight tiles (3 dx x hi/lo) for this dy
            const float4* src = reinterpret_cast<const float4*>(g_wt + dy * 6 * BTILE);
            float4* dst = reinterpret_cast<float4*>(smem + SM_B);
            for (int i = t; i < 6 * BTILE / 16; i += 256) dst[i] = src[i];
        }
        __syncthreads();

        const uint32_t sHi = sb + SM_A + (uint32_t)((orow + dy) * 2) * ATILE;
        const uint32_t sLo = sHi + ATILE;

#pragma unroll
        for (int ks = 0; ks < 4; ++ks) {
#pragma unroll
            for (int dx = 0; dx < 3; ++dx) {
                uint32_t bh[4][4], bl[4][4];
                const uint32_t bBase = sb + SM_B + (uint32_t)(dx * 2) * BTILE + ks * 32 + bLaneOff;
#pragma unroll
                for (int np = 0; np < 4; ++np) {
                    ldsm4(bh[np], bBase + np * 16 * ASTRIDE);
                    ldsm4(bl[np], bBase + BTILE + np * 16 * ASTRIDE);
                }
#pragma unroll
                for (int mt = 0; mt < 2; ++mt) {
                    const uint32_t arow = (uint32_t)(pxl + mt * 16 + dx);
                    uint32_t ah[4], al[4];
                    ldsm4(ah, sHi + arow * ASTRIDE + ks * 32 + aLaneOff);
                    ldsm4(al, sLo + arow * ASTRIDE + ks * 32 + aLaneOff);
#pragma unroll
                    for (int np = 0; np < 4; ++np) {
                        mma16816(acc[mt][2 * np],     ah, bh[np][0], bh[np][1]);
                        mma16816(acc[mt][2 * np + 1], ah, bh[np][2], bh[np][3]);
                        mma16816(acc[mt][2 * np],     ah, bl[np][0], bl[np][1]);
                        mma16816(acc[mt][2 * np + 1], ah, bl[np][2], bl[np][3]);
                        mma16816(acc[mt][2 * np],     al, bh[np][0], bh[np][1]);
                        mma16816(acc[mt][2 * np + 1], al, bh[np][2], bh[np][3]);
                    }
                }
            }
        }
    }

    // epilogue: bias + leaky relu, store NHWC
    const float* sbias = reinterpret_cast<const float*>(smem + SM_BIAS);
    const int y = y0 + orow;
    const int cq = (lane & 3) * 2;
    const int pxq = lane >> 2;
#pragma unroll
    for (int mt = 0; mt < 2; ++mt) {
#pragma unroll
        for (int half = 0; half < 2; ++half) {
            int px = pxl + mt * 16 + pxq + half * 8;
            float* dst = g_h + (((size_t)(b * HW) + y) * HW + px) * CC;
#pragma unroll
            for (int nt = 0; nt < 8; ++nt) {
                int co = nt * 8 + cq;
                float a0 = acc[mt][nt][half * 2 + 0] + sbias[co];
                float a1 = acc[mt][nt][half * 2 + 1] + sbias[co + 1];
                a0 = a0 > 0.f ? a0 : 0.02f * a0;
                a1 = a1 > 0.f ? a1 : 0.02f * a1;
                *reinterpret_cast<float2*>(dst + co) = make_float2(a0, a1);
            }
        }
    }
}

// ============================================================================
// Gather + FC: block per k (1000 blocks, 256 thr). Warp w handles b = 4w..4w+3.
// Weights staged per half (384 j x 24 o, padded stride 26), FFMA2 over o-pairs.
// ============================================================================
__global__ __launch_bounds__(256) void gather_fc_kernel(
    const int* __restrict__ pos,     // [K][B][L][2] (x, y)
    const float* __restrict__ pw,    // [24][768]
    const float* __restrict__ pb,    // [24]
    float* __restrict__ out)         // [K][B][24]
{
    __shared__ float wsm[384 * 26];  // 39,936 B

    const int t = threadIdx.x;
    const int lane = t & 31;
    const int w = t >> 5;
    const int k = blockIdx.x;
    const int b0 = w * 4;

    unsigned long long acc[4][12];
#pragma unroll
    for (int bi = 0; bi < 4; ++bi)
#pragma unroll
        for (int op = 0; op < 12; ++op) acc[bi][op] = 0ULL;

    for (int half = 0; half < 2; ++half) {
        __syncthreads();
        for (int i = t; i < 24 * 384; i += 256) {
            int o = i / 384;
            int jl = i - o * 384;
            wsm[jl * 26 + o] = pw[o * 768 + half * 384 + jl];
        }
        __syncthreads();

#pragma unroll
        for (int j24 = 0; j24 < 12; ++j24) {
            const int j24g = half * 12 + j24;
            const int l = j24g >> 1;
            const int coff = (j24g & 1) << 5;
            const float2* wrow = reinterpret_cast<const float2*>(&wsm[(j24 * 32 + lane) * 26]);
            float2 wv[12];
#pragma unroll
            for (int op = 0; op < 12; ++op) wv[op] = wrow[op];
#pragma unroll
            for (int bi = 0; bi < 4; ++bi) {
                const int b = b0 + bi;
                const int2 pp = *reinterpret_cast<const int2*>(&pos[((k * BBATCH + b) * LL + l) * 2]);
                int px = pp.x < 0 ? 0 : (pp.x > 127 ? 127 : pp.x);
                int py = pp.y < 0 ? 0 : (pp.y > 127 ? 127 : pp.y);
                float hv = g_h[(((size_t)(b * HW) + py) * HW + px) * CC + coff + lane];
                unsigned long long hv2 = pack2(hv, hv);
#pragma unroll
                for (int op = 0; op < 12; ++op)
                    acc[bi][op] = ffma2(pack2(wv[op].x, wv[op].y), hv2, acc[bi][op]);
            }
        }
    }

    // butterfly reduce over lanes (packed f32x2 adds)
#pragma unroll
    for (int bi = 0; bi < 4; ++bi)
#pragma unroll
        for (int op = 0; op < 12; ++op) {
            unsigned long long v = acc[bi][op];
#pragma unroll
            for (int m = 16; m > 0; m >>= 1) {
                double o = __shfl_xor_sync(0xffffffffu, __longlong_as_double((long long)v), m);
                v = addf2(v, (unsigned long long)__double_as_longlong(o));
            }
            acc[bi][op] = v;
        }

    // lane op (0..11) writes output pair (2op, 2op+1) for each of its 4 b's
#pragma unroll
    for (int bi = 0; bi < 4; ++bi) {
#pragma unroll
        for (int op = 0; op < 12; ++op) {
            if (lane == op) {
                float a0, a1;
                unpack2(acc[bi][op], a0, a1);
                float2 o2;
                o2.x = a0 + pb[2 * op];
                o2.y = a1 + pb[2 * op + 1];
                *reinterpret_cast<float2*>(&out[(size_t)((k * BBATCH + b0 + bi) * OO) + 2 * op]) = o2;
            }
        }
    }
}

// ============================================================================
extern "C" void kernel_launch(void* const* d_in, const int* in_sizes, int n_in,
                              void* d_out, int out_size) {
    const float* x   = (const float*)d_in[0];   // [32][64][128][128]
    const int*   pos = (const int*)  d_in[1];   // [1000][32][12][2]
    const float* cw  = (const float*)d_in[2];   // [64][64][3][3]
    const float* cb  = (const float*)d_in[3];   // [64]
    const float* pw  = (const float*)d_in[4];   // [24][768]
    const float* pb  = (const float*)d_in[5];   // [24]
    float* out = (float*)d_out;                 // [1000][32][24]

    cudaFuncSetAttribute(conv_tc_kernel, cudaFuncAttributeMaxDynamicSharedMemorySize, SM_TOT);

    wprep_kernel<<<(CC * CC * 9 + 255) / 256, 256>>>(cw);
    conv_tc_kernel<<<dim3(HW / 2, BBATCH), 256, SM_TOT>>>(x, cb);
    gather_fc_kernel<<<KK, 256>>>(pos, pw, pb, out);
}

// round 7
// speedup vs baseline: 1.4834x; 1.0073x over previous
#include <cuda_runtime.h>
#include <cuda_bf16.h>
#include <cstdint>

#define HW 128
#define CC 64
#define BBATCH 32
#define KK 1000
#define LL 12
#define OO 24

// h activations, NHWC fp32: [B][H][W][C] = 128 MB
__device__ float g_h[BBATCH * HW * HW * CC];
// pre-split bf16 weights, padded rows: [tap(9)][split(2)][co(64)][144 B]
__device__ unsigned char g_wt[18 * 9216];

// ===================== small helpers =====================
__device__ __forceinline__ uint32_t smem_u32(const void* p) {
    uint32_t a;
    asm("{ .reg .u64 t; cvta.to.shared.u64 t, %1; cvt.u32.u64 %0, t; }" : "=r"(a) : "l"(p));
    return a;
}
__device__ __forceinline__ unsigned long long ffma2(unsigned long long a,
                                                    unsigned long long b,
                                                    unsigned long long c) {
    unsigned long long d;
    asm("fma.rn.f32x2 %0, %1, %2, %3;" : "=l"(d) : "l"(a), "l"(b), "l"(c));
    return d;
}
__device__ __forceinline__ unsigned long long addf2(unsigned long long a, unsigned long long b) {
    unsigned long long d;
    asm("add.rn.f32x2 %0, %1, %2;" : "=l"(d) : "l"(a), "l"(b));
    return d;
}
__device__ __forceinline__ unsigned long long pack2(float lo, float hi) {
    unsigned long long d;
    asm("mov.b64 %0, {%1, %2};" : "=l"(d) : "f"(lo), "f"(hi));
    return d;
}
__device__ __forceinline__ void unpack2(unsigned long long v, float& lo, float& hi) {
    asm("mov.b64 {%0, %1}, %2;" : "=f"(lo), "=f"(hi) : "l"(v));
}
__device__ __forceinline__ void ldsm4(uint32_t* r, uint32_t a) {
    asm volatile("ldmatrix.sync.aligned.m8n8.x4.shared.b16 {%0,%1,%2,%3}, [%4];"
                 : "=r"(r[0]), "=r"(r[1]), "=r"(r[2]), "=r"(r[3]) : "r"(a));
}
__device__ __forceinline__ void mma16816(float* d, const uint32_t* a, uint32_t b0, uint32_t b1) {
    asm volatile("mma.sync.aligned.m16n8k16.row.col.f32.bf16.bf16.f32 "
                 "{%0,%1,%2,%3}, {%4,%5,%6,%7}, {%8,%9}, {%0,%1,%2,%3};"
                 : "+f"(d[0]), "+f"(d[1]), "+f"(d[2]), "+f"(d[3])
                 : "r"(a[0]), "r"(a[1]), "r"(a[2]), "r"(a[3]), "r"(b0), "r"(b1));
}

// ===================== conv smem layout (dynamic) =====================
#define ASTRIDE 144
#define ATILE (130 * 144)        // 18,720 B per (input-row slab, split)
#define BTILE (64 * 144)         // 9,216 B per (tap, split)
#define SM_B 0                   // 6 tiles for current dy: 55,296 B
#define SM_A 55296               // 8 slabs (4 rows x hi/lo): 149,760 B
#define SM_BIAS 205056           // 64 floats
#define SM_TOT 205312

// ============================================================================
// Prep: split conv_w into bf16 hi/lo, write padded [n=co][k=ci] tiles.
// ============================================================================
__global__ void wprep_kernel(const float* __restrict__ w) {
    int idx = blockIdx.x * 256 + threadIdx.x;
    if (idx >= CC * CC * 9) return;
    int co = idx / 576;
    int rem = idx - co * 576;
    int ci = rem / 9;
    int tap = rem - ci * 9;                 // dy*3 + dx
    float f = w[idx];
    __nv_bfloat16 hb = __float2bfloat16(f);
    __nv_bfloat16 lb = __float2bfloat16(f - __bfloat162float(hb));
    *reinterpret_cast<__nv_bfloat16*>(g_wt + (tap * 2 + 0) * BTILE + co * ASTRIDE + ci * 2) = hb;
    *reinterpret_cast<__nv_bfloat16*>(g_wt + (tap * 2 + 1) * BTILE + co * ASTRIDE + ci * 2) = lb;
}

// ============================================================================
// Conv via mma.sync bf16 (3-product fp32 split). CTA = (2 rows, image b).
// 8 warps; warp w: orow = w>>2, px base (w&3)*32, two m16 tiles.
// Inner schedule is TERM-MAJOR: 16 independent accumulator targets between
// reuses of the same acc -> HMMA RAW latency hidden at low occupancy.
// ============================================================================
__global__ __launch_bounds__(256, 1) void conv_tc_kernel(
    const float* __restrict__ x,     // [B][C][H][W]
    const float* __restrict__ bias)  // [C]
{
    extern __shared__ unsigned char smem[];
    const uint32_t sb = smem_u32(smem);
    const int t = threadIdx.x;
    const int lane = t & 31;
    const int w = t >> 5;
    const int y0 = blockIdx.x * 2;
    const int b = blockIdx.y;
    const int orow = w >> 2;
    const int pxl = (w & 3) * 32;

    // bias
    if (t < 64) *reinterpret_cast<float*>(smem + SM_BIAS + t * 4) = bias[t];

    // zero horizontal halo rows (px=-1 and px=128) of all 8 A slabs
    for (int i = t; i < 8 * 128; i += 256) {
        int slab = i >> 7;
        int rem = i & 127;
        int row = (rem >> 6) ? 129 : 0;
        int ci = rem & 63;
        *reinterpret_cast<uint16_t*>(smem + SM_A + slab * ATILE + row * ASTRIDE + ci * 2) = 0;
    }

    // stage A: 4 input rows (y0-1 .. y0+2) -> [px][ci] bf16 hi/lo slabs
    for (int i = t; i < 4 * CC * HW; i += 256) {
        int px = i & 127;
        int ci = (i >> 7) & 63;
        int r = i >> 13;
        int yin = y0 - 1 + r;
        float f = 0.f;
        if ((unsigned)yin < 128u)
            f = x[((size_t)(b * CC + ci) * HW + yin) * HW + px];
        __nv_bfloat16 hb = __float2bfloat16(f);
        __nv_bfloat16 lb = __float2bfloat16(f - __bfloat162float(hb));
        unsigned char* p = smem + SM_A + (r * 2) * ATILE + (px + 1) * ASTRIDE + ci * 2;
        *reinterpret_cast<__nv_bfloat16*>(p) = hb;
        *reinterpret_cast<__nv_bfloat16*>(p + ATILE) = lb;
    }

    // per-lane ldmatrix address components
    const uint32_t aLaneOff = (uint32_t)((lane & 15) * ASTRIDE + (lane >> 4) * 16);
    const uint32_t bLaneOff = (uint32_t)((((lane & 7) + ((lane >> 4) << 3)) * ASTRIDE) +
                                         ((lane >> 3) & 1) * 16);

    float acc[2][8][4];
#pragma unroll
    for (int mt = 0; mt < 2; ++mt)
#pragma unroll
        for (int nt = 0; nt < 8; ++nt)
#pragma unroll
            for (int q = 0; q < 4; ++q) acc[mt][nt][q] = 0.f;

    for (int dy = 0; dy < 3; ++dy) {
        __syncthreads();
        {   // stage 6 weight tiles (3 dx x hi/lo) for this dy
            const float4* src = reinterpret_cast<const float4*>(g_wt + dy * 6 * BTILE);
            float4* dst = reinterpret_cast<float4*>(smem + SM_B);
            for (int i = t; i < 6 * BTILE / 16; i += 256) dst[i] = src[i];
        }
        __syncthreads();

        const uint32_t sHi = sb + SM_A + (uint32_t)((orow + dy) * 2) * ATILE;
        const uint32_t sLo = sHi + ATILE;

#pragma unroll
        for (int ks = 0; ks < 4; ++ks) {
#pragma unroll
            for (int dx = 0; dx < 3; ++dx) {
                // ---- load all fragments for this (ks, dx) ----
                uint32_t bh[4][4], bl[4][4];
                const uint32_t bBase = sb + SM_B + (uint32_t)(dx * 2) * BTILE + ks * 32 + bLaneOff;
#pragma unroll
                for (int np = 0; np < 4; ++np) {
                    ldsm4(bh[np], bBase + np * 16 * ASTRIDE);
                    ldsm4(bl[np], bBase + BTILE + np * 16 * ASTRIDE);
                }
                uint32_t ah[2][4], al[2][4];
#pragma unroll
                for (int mt = 0; mt < 2; ++mt) {
                    const uint32_t arow = (uint32_t)(pxl + mt * 16 + dx);
                    ldsm4(ah[mt], sHi + arow * ASTRIDE + ks * 32 + aLaneOff);
                    ldsm4(al[mt], sLo + arow * ASTRIDE + ks * 32 + aLaneOff);
                }
                // ---- term 0: x_hi * w_hi  (16 independent MMAs) ----
#pragma unroll
                for (int mt = 0; mt < 2; ++mt)
#pragma unroll
                    for (int np = 0; np < 4; ++np) {
                        mma16816(acc[mt][2 * np],     ah[mt], bh[np][0], bh[np][1]);
                        mma16816(acc[mt][2 * np + 1], ah[mt], bh[np][2], bh[np][3]);
                    }
                // ---- term 1: x_hi * w_lo ----
#pragma unroll
                for (int mt = 0; mt < 2; ++mt)
#pragma unroll
                    for (int np = 0; np < 4; ++np) {
                        mma16816(acc[mt][2 * np],     ah[mt], bl[np][0], bl[np][1]);
                        mma16816(acc[mt][2 * np + 1], ah[mt], bl[np][2], bl[np][3]);
                    }
                // ---- term 2: x_lo * w_hi ----
#pragma unroll
                for (int mt = 0; mt < 2; ++mt)
#pragma unroll
                    for (int np = 0; np < 4; ++np) {
                        mma16816(acc[mt][2 * np],     al[mt], bh[np][0], bh[np][1]);
                        mma16816(acc[mt][2 * np + 1], al[mt], bh[np][2], bh[np][3]);
                    }
            }
        }
    }

    // epilogue: bias + leaky relu, store NHWC
    const float* sbias = reinterpret_cast<const float*>(smem + SM_BIAS);
    const int y = y0 + orow;
    const int cq = (lane & 3) * 2;
    const int pxq = lane >> 2;
#pragma unroll
    for (int mt = 0; mt < 2; ++mt) {
#pragma unroll
        for (int half = 0; half < 2; ++half) {
            int px = pxl + mt * 16 + pxq + half * 8;
            float* dst = g_h + (((size_t)(b * HW) + y) * HW + px) * CC;
#pragma unroll
            for (int nt = 0; nt < 8; ++nt) {
                int co = nt * 8 + cq;
                float a0 = acc[mt][nt][half * 2 + 0] + sbias[co];
                float a1 = acc[mt][nt][half * 2 + 1] + sbias[co + 1];
                a0 = a0 > 0.f ? a0 : 0.02f * a0;
                a1 = a1 > 0.f ? a1 : 0.02f * a1;
                *reinterpret_cast<float2*>(dst + co) = make_float2(a0, a1);
            }
        }
    }
}

// ============================================================================
// Gather + FC: block per k (1000 blocks, 256 thr). Warp w handles b = 4w..4w+3.
// ============================================================================
__global__ __launch_bounds__(256) void gather_fc_kernel(
    const int* __restrict__ pos,     // [K][B][L][2] (x, y)
    const float* __restrict__ pw,    // [24][768]
    const float* __restrict__ pb,    // [24]
    float* __restrict__ out)         // [K][B][24]
{
    __shared__ float wsm[384 * 26];  // 39,936 B

    const int t = threadIdx.x;
    const int lane = t & 31;
    const int w = t >> 5;
    const int k = blockIdx.x;
    const int b0 = w * 4;

    unsigned long long acc[4][12];
#pragma unroll
    for (int bi = 0; bi < 4; ++bi)
#pragma unroll
        for (int op = 0; op < 12; ++op) acc[bi][op] = 0ULL;

    for (int half = 0; half < 2; ++half) {
        __syncthreads();
        for (int i = t; i < 24 * 384; i += 256) {
            int o = i / 384;
            int jl = i - o * 384;
            wsm[jl * 26 + o] = pw[o * 768 + half * 384 + jl];
        }
        __syncthreads();

#pragma unroll
        for (int j24 = 0; j24 < 12; ++j24) {
            const int j24g = half * 12 + j24;
            const int l = j24g >> 1;
            const int coff = (j24g & 1) << 5;
            const float2* wrow = reinterpret_cast<const float2*>(&wsm[(j24 * 32 + lane) * 26]);
            float2 wv[12];
#pragma unroll
            for (int op = 0; op < 12; ++op) wv[op] = wrow[op];
#pragma unroll
            for (int bi = 0; bi < 4; ++bi) {
                const int b = b0 + bi;
                const int2 pp = *reinterpret_cast<const int2*>(&pos[((k * BBATCH + b) * LL + l) * 2]);
                int px = pp.x < 0 ? 0 : (pp.x > 127 ? 127 : pp.x);
                int py = pp.y < 0 ? 0 : (pp.y > 127 ? 127 : pp.y);
                float hv = g_h[(((size_t)(b * HW) + py) * HW + px) * CC + coff + lane];
                unsigned long long hv2 = pack2(hv, hv);
#pragma unroll
                for (int op = 0; op < 12; ++op)
                    acc[bi][op] = ffma2(pack2(wv[op].x, wv[op].y), hv2, acc[bi][op]);
            }
        }
    }

    // butterfly reduce over lanes (packed f32x2 adds)
#pragma unroll
    for (int bi = 0; bi < 4; ++bi)
#pragma unroll
        for (int op = 0; op < 12; ++op) {
            unsigned long long v = acc[bi][op];
#pragma unroll
            for (int m = 16; m > 0; m >>= 1) {
                double o = __shfl_xor_sync(0xffffffffu, __longlong_as_double((long long)v), m);
                v = addf2(v, (unsigned long long)__double_as_longlong(o));
            }
            acc[bi][op] = v;
        }

    // lane op (0..11) writes output pair (2op, 2op+1) for each of its 4 b's
#pragma unroll
    for (int bi = 0; bi < 4; ++bi) {
#pragma unroll
        for (int op = 0; op < 12; ++op) {
            if (lane == op) {
                float a0, a1;
                unpack2(acc[bi][op], a0, a1);
                float2 o2;
                o2.x = a0 + pb[2 * op];
                o2.y = a1 + pb[2 * op + 1];
                *reinterpret_cast<float2*>(&out[(size_t)((k * BBATCH + b0 + bi) * OO) + 2 * op]) = o2;
            }
        }
    }
}

// ============================================================================
extern "C" void kernel_launch(void* const* d_in, const int* in_sizes, int n_in,
                              void* d_out, int out_size) {
    const float* x   = (const float*)d_in[0];   // [32][64][128][128]
    const int*   pos = (const int*)  d_in[1];   // [1000][32][12][2]
    const float* cw  = (const float*)d_in[2];   // [64][64][3][3]
    const float* cb  = (const float*)d_in[3];   // [64]
    const float* pw  = (const float*)d_in[4];   // [24][768]
    const float* pb  = (const float*)d_in[5];   // [24]
    float* out = (float*)d_out;                 // [1000][32][24]

    cudaFuncSetAttribute(conv_tc_kernel, cudaFuncAttributeMaxDynamicSharedMemorySize, SM_TOT);

    wprep_kernel<<<(CC * CC * 9 + 255) / 256, 256>>>(cw);
    conv_tc_kernel<<<dim3(HW / 2, BBATCH), 256, SM_TOT>>>(x, cb);
    gather_fc_kernel<<<KK, 256>>>(pos, pw, pb, out);
}

// round 8
// speedup vs baseline: 2.6629x; 1.7952x over previous
#include <cuda_runtime.h>
#include <cuda_fp16.h>
#include <cstdint>

#define HW 128
#define CC 64
#define BBATCH 32
#define KK 1000
#define LL 12
#define OO 24

// h activations, NHWC fp32: [B][H][W][C] = 128 MB
__device__ float g_h[BBATCH * HW * HW * CC];
// fp16 weights, padded rows: [tap(9)][co(64)][144 B] (72 fp16 slots, 64 used)
__device__ unsigned char g_wt[9 * 9216];

// ===================== small helpers =====================
__device__ __forceinline__ uint32_t smem_u32(const void* p) {
    uint32_t a;
    asm("{ .reg .u64 t; cvta.to.shared.u64 t, %1; cvt.u32.u64 %0, t; }" : "=r"(a) : "l"(p));
    return a;
}
__device__ __forceinline__ unsigned long long ffma2(unsigned long long a,
                                                    unsigned long long b,
                                                    unsigned long long c) {
    unsigned long long d;
    asm("fma.rn.f32x2 %0, %1, %2, %3;" : "=l"(d) : "l"(a), "l"(b), "l"(c));
    return d;
}
__device__ __forceinline__ unsigned long long addf2(unsigned long long a, unsigned long long b) {
    unsigned long long d;
    asm("add.rn.f32x2 %0, %1, %2;" : "=l"(d) : "l"(a), "l"(b));
    return d;
}
__device__ __forceinline__ unsigned long long pack2(float lo, float hi) {
    unsigned long long d;
    asm("mov.b64 %0, {%1, %2};" : "=l"(d) : "f"(lo), "f"(hi));
    return d;
}
__device__ __forceinline__ void unpack2(unsigned long long v, float& lo, float& hi) {
    asm("mov.b64 {%0, %1}, %2;" : "=f"(lo), "=f"(hi) : "l"(v));
}
__device__ __forceinline__ void ldsm4(uint32_t* r, uint32_t a) {
    asm volatile("ldmatrix.sync.aligned.m8n8.x4.shared.b16 {%0,%1,%2,%3}, [%4];"
                 : "=r"(r[0]), "=r"(r[1]), "=r"(r[2]), "=r"(r[3]) : "r"(a));
}
__device__ __forceinline__ void mma16816h(float* d, const uint32_t* a, uint32_t b0, uint32_t b1) {
    asm volatile("mma.sync.aligned.m16n8k16.row.col.f32.f16.f16.f32 "
                 "{%0,%1,%2,%3}, {%4,%5,%6,%7}, {%8,%9}, {%0,%1,%2,%3};"
                 : "+f"(d[0]), "+f"(d[1]), "+f"(d[2]), "+f"(d[3])
                 : "r"(a[0]), "r"(a[1]), "r"(a[2]), "r"(a[3]), "r"(b0), "r"(b1));
}

// ===================== conv smem layout (dynamic) =====================
#define ASTRIDE 144
#define ATILE (130 * 144)        // 18,720 B per input-row slab (fp16)
#define BTILE (64 * 144)         // 9,216 B per tap
#define SM_B 0                   // 3 tiles for current dy: 27,648 B
#define SM_A 27648               // 4 slabs: 74,880 B -> ends 102,528
#define SM_BIAS 102528           // 64 floats
#define SM_TOT 102784

// ============================================================================
// Prep: convert conv_w to fp16, write padded [n=co][k=ci] tiles per tap.
// ============================================================================
__global__ void wprep_kernel(const float* __restrict__ w) {
    int idx = blockIdx.x * 256 + threadIdx.x;
    if (idx >= CC * CC * 9) return;
    int co = idx / 576;
    int rem = idx - co * 576;
    int ci = rem / 9;
    int tap = rem - ci * 9;                 // dy*3 + dx
    *reinterpret_cast<__half*>(g_wt + tap * BTILE + co * ASTRIDE + ci * 2) =
        __float2half(w[idx]);
}

// ============================================================================
// Conv via mma.sync fp16 single-pass. CTA = (2 rows, image b), 8 warps.
// warp w: orow = w>>2, px base (w&3)*32, two m16 tiles.
// ============================================================================
__global__ __launch_bounds__(256) void conv_tc_kernel(
    const float* __restrict__ x,     // [B][C][H][W]
    const float* __restrict__ bias)  // [C]
{
    extern __shared__ unsigned char smem[];
    const uint32_t sb = smem_u32(smem);
    const int t = threadIdx.x;
    const int lane = t & 31;
    const int w = t >> 5;
    const int y0 = blockIdx.x * 2;
    const int b = blockIdx.y;
    const int orow = w >> 2;
    const int pxl = (w & 3) * 32;

    // bias
    if (t < 64) *reinterpret_cast<float*>(smem + SM_BIAS + t * 4) = bias[t];

    // zero horizontal halo rows (px=-1 and px=128) of all 4 A slabs
    for (int i = t; i < 4 * 128; i += 256) {
        int slab = i >> 7;
        int rem = i & 127;
        int row = (rem >> 6) ? 129 : 0;
        int ci = rem & 63;
        *reinterpret_cast<uint16_t*>(smem + SM_A + slab * ATILE + row * ASTRIDE + ci * 2) = 0;
    }

    // stage A: 4 input rows (y0-1 .. y0+2) -> [px][ci] fp16 slabs
    for (int i = t; i < 4 * CC * HW; i += 256) {
        int px = i & 127;
        int ci = (i >> 7) & 63;
        int r = i >> 13;
        int yin = y0 - 1 + r;
        float f = 0.f;
        if ((unsigned)yin < 128u)
            f = x[((size_t)(b * CC + ci) * HW + yin) * HW + px];
        *reinterpret_cast<__half*>(smem + SM_A + r * ATILE + (px + 1) * ASTRIDE + ci * 2) =
            __float2half(f);
    }

    // per-lane ldmatrix address components
    const uint32_t aLaneOff = (uint32_t)((lane & 15) * ASTRIDE + (lane >> 4) * 16);
    const uint32_t bLaneOff = (uint32_t)((((lane & 7) + ((lane >> 4) << 3)) * ASTRIDE) +
                                         ((lane >> 3) & 1) * 16);

    float acc[2][8][4];
#pragma unroll
    for (int mt = 0; mt < 2; ++mt)
#pragma unroll
        for (int nt = 0; nt < 8; ++nt)
#pragma unroll
            for (int q = 0; q < 4; ++q) acc[mt][nt][q] = 0.f;

    for (int dy = 0; dy < 3; ++dy) {
        __syncthreads();
        {   // stage 3 weight tiles (3 dx) for this dy
            const float4* src = reinterpret_cast<const float4*>(g_wt + dy * 3 * BTILE);
            float4* dst = reinterpret_cast<float4*>(smem + SM_B);
            for (int i = t; i < 3 * BTILE / 16; i += 256) dst[i] = src[i];
        }
        __syncthreads();

        const uint32_t sA = sb + SM_A + (uint32_t)(orow + dy) * ATILE;

#pragma unroll
        for (int ks = 0; ks < 4; ++ks) {
#pragma unroll
            for (int dx = 0; dx < 3; ++dx) {
                uint32_t bf[4][4];
                const uint32_t bBase = sb + SM_B + (uint32_t)dx * BTILE + ks * 32 + bLaneOff;
#pragma unroll
                for (int np = 0; np < 4; ++np)
                    ldsm4(bf[np], bBase + np * 16 * ASTRIDE);
                uint32_t af[2][4];
#pragma unroll
                for (int mt = 0; mt < 2; ++mt) {
                    const uint32_t arow = (uint32_t)(pxl + mt * 16 + dx);
                    ldsm4(af[mt], sA + arow * ASTRIDE + ks * 32 + aLaneOff);
                }
#pragma unroll
                for (int mt = 0; mt < 2; ++mt)
#pragma unroll
                    for (int np = 0; np < 4; ++np) {
                        mma16816h(acc[mt][2 * np],     af[mt], bf[np][0], bf[np][1]);
                        mma16816h(acc[mt][2 * np + 1], af[mt], bf[np][2], bf[np][3]);
                    }
            }
        }
    }

    // epilogue: bias + leaky relu, store NHWC
    const float* sbias = reinterpret_cast<const float*>(smem + SM_BIAS);
    const int y = y0 + orow;
    const int cq = (lane & 3) * 2;
    const int pxq = lane >> 2;
#pragma unroll
    for (int mt = 0; mt < 2; ++mt) {
#pragma unroll
        for (int half = 0; half < 2; ++half) {
            int px = pxl + mt * 16 + pxq + half * 8;
            float* dst = g_h + (((size_t)(b * HW) + y) * HW + px) * CC;
#pragma unroll
            for (int nt = 0; nt < 8; ++nt) {
                int co = nt * 8 + cq;
                float a0 = acc[mt][nt][half * 2 + 0] + sbias[co];
                float a1 = acc[mt][nt][half * 2 + 1] + sbias[co + 1];
                a0 = a0 > 0.f ? a0 : 0.02f * a0;
                a1 = a1 > 0.f ? a1 : 0.02f * a1;
                *reinterpret_cast<float2*>(dst + co) = make_float2(a0, a1);
            }
        }
    }
}

// ============================================================================
// Gather + FC: block per k (1000 blocks, 256 thr). Warp w handles b = 4w..4w+3.
// ============================================================================
__global__ __launch_bounds__(256) void gather_fc_kernel(
    const int* __restrict__ pos,     // [K][B][L][2] (x, y)
    const float* __restrict__ pw,    // [24][768]
    const float* __restrict__ pb,    // [24]
    float* __restrict__ out)         // [K][B][24]
{
    __shared__ float wsm[384 * 26];  // 39,936 B

    const int t = threadIdx.x;
    const int lane = t & 31;
    const int w = t >> 5;
    const int k = blockIdx.x;
    const int b0 = w * 4;

    unsigned long long acc[4][12];
#pragma unroll
    for (int bi = 0; bi < 4; ++bi)
#pragma unroll
        for (int op = 0; op < 12; ++op) acc[bi][op] = 0ULL;

    for (int half = 0; half < 2; ++half) {
        __syncthreads();
        for (int i = t; i < 24 * 384; i += 256) {
            int o = i / 384;
            int jl = i - o * 384;
            wsm[jl * 26 + o] = pw[o * 768 + half * 384 + jl];
        }
        __syncthreads();

#pragma unroll
        for (int j24 = 0; j24 < 12; ++j24) {
            const int j24g = half * 12 + j24;
            const int l = j24g >> 1;
            const int coff = (j24g & 1) << 5;
            const float2* wrow = reinterpret_cast<const float2*>(&wsm[(j24 * 32 + lane) * 26]);
            float2 wv[12];
#pragma unroll
            for (int op = 0; op < 12; ++op) wv[op] = wrow[op];
#pragma unroll
            for (int bi = 0; bi < 4; ++bi) {
                const int b = b0 + bi;
                const int2 pp = *reinterpret_cast<const int2*>(&pos[((k * BBATCH + b) * LL + l) * 2]);
                int px = pp.x < 0 ? 0 : (pp.x > 127 ? 127 : pp.x);
                int py = pp.y < 0 ? 0 : (pp.y > 127 ? 127 : pp.y);
                float hv = g_h[(((size_t)(b * HW) + py) * HW + px) * CC + coff + lane];
                unsigned long long hv2 = pack2(hv, hv);
#pragma unroll
                for (int op = 0; op < 12; ++op)
                    acc[bi][op] = ffma2(pack2(wv[op].x, wv[op].y), hv2, acc[bi][op]);
            }
        }
    }

    // butterfly reduce over lanes (packed f32x2 adds)
#pragma unroll
    for (int bi = 0; bi < 4; ++bi)
#pragma unroll
        for (int op = 0; op < 12; ++op) {
            unsigned long long v = acc[bi][op];
#pragma unroll
            for (int m = 16; m > 0; m >>= 1) {
                double o = __shfl_xor_sync(0xffffffffu, __longlong_as_double((long long)v), m);
                v = addf2(v, (unsigned long long)__double_as_longlong(o));
            }
            acc[bi][op] = v;
        }

    // lane op (0..11) writes output pair (2op, 2op+1) for each of its 4 b's
#pragma unroll
    for (int bi = 0; bi < 4; ++bi) {
#pragma unroll
        for (int op = 0; op < 12; ++op) {
            if (lane == op) {
                float a0, a1;
                unpack2(acc[bi][op], a0, a1);
                float2 o2;
                o2.x = a0 + pb[2 * op];
                o2.y = a1 + pb[2 * op + 1];
                *reinterpret_cast<float2*>(&out[(size_t)((k * BBATCH + b0 + bi) * OO) + 2 * op]) = o2;
            }
        }
    }
}

// ============================================================================
extern "C" void kernel_launch(void* const* d_in, const int* in_sizes, int n_in,
                              void* d_out, int out_size) {
    const float* x   = (const float*)d_in[0];   // [32][64][128][128]
    const int*   pos = (const int*)  d_in[1];   // [1000][32][12][2]
    const float* cw  = (const float*)d_in[2];   // [64][64][3][3]
    const float* cb  = (const float*)d_in[3];   // [64]
    const float* pw  = (const float*)d_in[4];   // [24][768]
    const float* pb  = (const float*)d_in[5];   // [24]
    float* out = (float*)d_out;                 // [1000][32][24]

    cudaFuncSetAttribute(conv_tc_kernel, cudaFuncAttributeMaxDynamicSharedMemorySize, SM_TOT);

    wprep_kernel<<<(CC * CC * 9 + 255) / 256, 256>>>(cw);
    conv_tc_kernel<<<dim3(HW / 2, BBATCH), 256, SM_TOT>>>(x, cb);
    gather_fc_kernel<<<KK, 256>>>(pos, pw, pb, out);
}

// round 9
// speedup vs baseline: 2.7928x; 1.0488x over previous
#include <cuda_runtime.h>
#include <cuda_fp16.h>
#include <cstdint>

#define HW 128
#define CC 64
#define BBATCH 32
#define KK 1000
#define LL 12
#define OO 24

// h activations, NHWC fp32: [B][H][W][C] = 128 MB
__device__ float g_h[BBATCH * HW * HW * CC];
// fp16 weights, padded rows: [tap(9)][co(64)][144 B] (72 fp16 slots, 64 used)
__device__ unsigned char g_wt[9 * 9216];

// ===================== small helpers =====================
__device__ __forceinline__ uint32_t smem_u32(const void* p) {
    uint32_t a;
    asm("{ .reg .u64 t; cvta.to.shared.u64 t, %1; cvt.u32.u64 %0, t; }" : "=r"(a) : "l"(p));
    return a;
}
__device__ __forceinline__ unsigned long long ffma2(unsigned long long a,
                                                    unsigned long long b,
                                                    unsigned long long c) {
    unsigned long long d;
    asm("fma.rn.f32x2 %0, %1, %2, %3;" : "=l"(d) : "l"(a), "l"(b), "l"(c));
    return d;
}
__device__ __forceinline__ unsigned long long addf2(unsigned long long a, unsigned long long b) {
    unsigned long long d;
    asm("add.rn.f32x2 %0, %1, %2;" : "=l"(d) : "l"(a), "l"(b));
    return d;
}
__device__ __forceinline__ unsigned long long pack2(float lo, float hi) {
    unsigned long long d;
    asm("mov.b64 %0, {%1, %2};" : "=l"(d) : "f"(lo), "f"(hi));
    return d;
}
__device__ __forceinline__ void unpack2(unsigned long long v, float& lo, float& hi) {
    asm("mov.b64 {%0, %1}, %2;" : "=f"(lo), "=f"(hi) : "l"(v));
}
__device__ __forceinline__ void ldsm4(uint32_t* r, uint32_t a) {
    asm volatile("ldmatrix.sync.aligned.m8n8.x4.shared.b16 {%0,%1,%2,%3}, [%4];"
                 : "=r"(r[0]), "=r"(r[1]), "=r"(r[2]), "=r"(r[3]) : "r"(a));
}
__device__ __forceinline__ void mma16816h(float* d, const uint32_t* a, uint32_t b0, uint32_t b1) {
    asm volatile("mma.sync.aligned.m16n8k16.row.col.f32.f16.f16.f32 "
                 "{%0,%1,%2,%3}, {%4,%5,%6,%7}, {%8,%9}, {%0,%1,%2,%3};"
                 : "+f"(d[0]), "+f"(d[1]), "+f"(d[2]), "+f"(d[3])
                 : "r"(a[0]), "r"(a[1]), "r"(a[2]), "r"(a[3]), "r"(b0), "r"(b1));
}

// ===================== conv smem layout (dynamic) =====================
#define ASTRIDE 144
#define ATILE (130 * 144)        // 18,720 B per input-row slab (fp16)
#define BTILE (64 * 144)         // 9,216 B per tap
#define SM_B 0                   // 3 tiles for current dy: 27,648 B
#define SM_A 27648               // 4 slabs: 74,880 B -> ends 102,528
#define SM_BIAS 102528           // 64 floats
#define SM_TOT 102784

// ============================================================================
// Prep: convert conv_w to fp16, write padded [n=co][k=ci] tiles per tap.
// ============================================================================
__global__ void wprep_kernel(const float* __restrict__ w) {
    int idx = blockIdx.x * 256 + threadIdx.x;
    if (idx >= CC * CC * 9) return;
    int co = idx / 576;
    int rem = idx - co * 576;
    int ci = rem / 9;
    int tap = rem - ci * 9;                 // dy*3 + dx
    *reinterpret_cast<__half*>(g_wt + tap * BTILE + co * ASTRIDE + ci * 2) =
        __float2half(w[idx]);
}

// ============================================================================
// Conv via mma.sync fp16 single-pass. CTA = (2 rows, image b), 8 warps.
// (unchanged from the 377us round — protected)
// ============================================================================
__global__ __launch_bounds__(256) void conv_tc_kernel(
    const float* __restrict__ x,     // [B][C][H][W]
    const float* __restrict__ bias)  // [C]
{
    extern __shared__ unsigned char smem[];
    const uint32_t sb = smem_u32(smem);
    const int t = threadIdx.x;
    const int lane = t & 31;
    const int w = t >> 5;
    const int y0 = blockIdx.x * 2;
    const int b = blockIdx.y;
    const int orow = w >> 2;
    const int pxl = (w & 3) * 32;

    if (t < 64) *reinterpret_cast<float*>(smem + SM_BIAS + t * 4) = bias[t];

    for (int i = t; i < 4 * 128; i += 256) {
        int slab = i >> 7;
        int rem = i & 127;
        int row = (rem >> 6) ? 129 : 0;
        int ci = rem & 63;
        *reinterpret_cast<uint16_t*>(smem + SM_A + slab * ATILE + row * ASTRIDE + ci * 2) = 0;
    }

    for (int i = t; i < 4 * CC * HW; i += 256) {
        int px = i & 127;
        int ci = (i >> 7) & 63;
        int r = i >> 13;
        int yin = y0 - 1 + r;
        float f = 0.f;
        if ((unsigned)yin < 128u)
            f = x[((size_t)(b * CC + ci) * HW + yin) * HW + px];
        *reinterpret_cast<__half*>(smem + SM_A + r * ATILE + (px + 1) * ASTRIDE + ci * 2) =
            __float2half(f);
    }

    const uint32_t aLaneOff = (uint32_t)((lane & 15) * ASTRIDE + (lane >> 4) * 16);
    const uint32_t bLaneOff = (uint32_t)((((lane & 7) + ((lane >> 4) << 3)) * ASTRIDE) +
                                         ((lane >> 3) & 1) * 16);

    float acc[2][8][4];
#pragma unroll
    for (int mt = 0; mt < 2; ++mt)
#pragma unroll
        for (int nt = 0; nt < 8; ++nt)
#pragma unroll
            for (int q = 0; q < 4; ++q) acc[mt][nt][q] = 0.f;

    for (int dy = 0; dy < 3; ++dy) {
        __syncthreads();
        {
            const float4* src = reinterpret_cast<const float4*>(g_wt + dy * 3 * BTILE);
            float4* dst = reinterpret_cast<float4*>(smem + SM_B);
            for (int i = t; i < 3 * BTILE / 16; i += 256) dst[i] = src[i];
        }
        __syncthreads();

        const uint32_t sA = sb + SM_A + (uint32_t)(orow + dy) * ATILE;

#pragma unroll
        for (int ks = 0; ks < 4; ++ks) {
#pragma unroll
            for (int dx = 0; dx < 3; ++dx) {
                uint32_t bf[4][4];
                const uint32_t bBase = sb + SM_B + (uint32_t)dx * BTILE + ks * 32 + bLaneOff;
#pragma unroll
                for (int np = 0; np < 4; ++np)
                    ldsm4(bf[np], bBase + np * 16 * ASTRIDE);
                uint32_t af[2][4];
#pragma unroll
                for (int mt = 0; mt < 2; ++mt) {
                    const uint32_t arow = (uint32_t)(pxl + mt * 16 + dx);
                    ldsm4(af[mt], sA + arow * ASTRIDE + ks * 32 + aLaneOff);
                }
#pragma unroll
                for (int mt = 0; mt < 2; ++mt)
#pragma unroll
                    for (int np = 0; np < 4; ++np) {
                        mma16816h(acc[mt][2 * np],     af[mt], bf[np][0], bf[np][1]);
                        mma16816h(acc[mt][2 * np + 1], af[mt], bf[np][2], bf[np][3]);
                    }
            }
        }
    }

    const float* sbias = reinterpret_cast<const float*>(smem + SM_BIAS);
    const int y = y0 + orow;
    const int cq = (lane & 3) * 2;
    const int pxq = lane >> 2;
#pragma unroll
    for (int mt = 0; mt < 2; ++mt) {
#pragma unroll
        for (int half = 0; half < 2; ++half) {
            int px = pxl + mt * 16 + pxq + half * 8;
            float* dst = g_h + (((size_t)(b * HW) + y) * HW + px) * CC;
#pragma unroll
            for (int nt = 0; nt < 8; ++nt) {
                int co = nt * 8 + cq;
                float a0 = acc[mt][nt][half * 2 + 0] + sbias[co];
                float a1 = acc[mt][nt][half * 2 + 1] + sbias[co + 1];
                a0 = a0 > 0.f ? a0 : 0.02f * a0;
                a1 = a1 > 0.f ? a1 : 0.02f * a1;
                *reinterpret_cast<float2*>(dst + co) = make_float2(a0, a1);
            }
        }
    }
}

// ============================================================================
// Gather + FC v3: block per k, warp per 4 b's, software-pipelined loads.
// Per half (6 l-pairs): prefetch block p+1's (4 pos + 8 h) loads while
// FFMAing block p -> pos->h dependent-latency chain pulled off critical path.
// ============================================================================
__global__ __launch_bounds__(256) void gather_fc_kernel(
    const int* __restrict__ pos,     // [K][B][L][2] (x, y)
    const float* __restrict__ pw,    // [24][768]
    const float* __restrict__ pb,    // [24]
    float* __restrict__ out)         // [K][B][24]
{
    __shared__ float wsm[384 * 26];  // 39,936 B

    const int t = threadIdx.x;
    const int lane = t & 31;
    const int w = t >> 5;
    const int k = blockIdx.x;
    const int b0 = w * 4;

    const int2* __restrict__ pos2 = reinterpret_cast<const int2*>(pos);

    unsigned long long acc[4][12];
#pragma unroll
    for (int bi = 0; bi < 4; ++bi)
#pragma unroll
        for (int op = 0; op < 12; ++op) acc[bi][op] = 0ULL;

    // hbuf[parity][jj*4 + bi]: jj = coff half (0 -> c 0..31, 1 -> c 32..63)
    float hbuf[2][8];

    for (int half = 0; half < 2; ++half) {
        __syncthreads();
        for (int i = t; i < 24 * 384; i += 256) {
            int o = i / 384;
            int jl = i - o * 384;
            wsm[jl * 26 + o] = pw[o * 768 + half * 384 + jl];
        }
        __syncthreads();

        // prefetch block p=0
        {
            const int l = half * 6;
#pragma unroll
            for (int bi = 0; bi < 4; ++bi) {
                const int b = b0 + bi;
                int2 pp = pos2[(k * BBATCH + b) * LL + l];
                int px = pp.x < 0 ? 0 : (pp.x > 127 ? 127 : pp.x);
                int py = pp.y < 0 ? 0 : (pp.y > 127 ? 127 : pp.y);
                const float* hp = &g_h[(((size_t)(b * HW) + py) * HW + px) * CC + lane];
                hbuf[0][bi]     = hp[0];
                hbuf[0][4 + bi] = hp[32];
            }
        }

#pragma unroll
        for (int p = 0; p < 6; ++p) {
            // prefetch block p+1 into the other buffer
            if (p < 5) {
                const int l = half * 6 + p + 1;
#pragma unroll
                for (int bi = 0; bi < 4; ++bi) {
                    const int b = b0 + bi;
                    int2 pp = pos2[(k * BBATCH + b) * LL + l];
                    int px = pp.x < 0 ? 0 : (pp.x > 127 ? 127 : pp.x);
                    int py = pp.y < 0 ? 0 : (pp.y > 127 ? 127 : pp.y);
                    const float* hp = &g_h[(((size_t)(b * HW) + py) * HW + px) * CC + lane];
                    hbuf[(p + 1) & 1][bi]     = hp[0];
                    hbuf[(p + 1) & 1][4 + bi] = hp[32];
                }
            }
            // consume block p: j24 = 2p (coff 0) and 2p+1 (coff 32)
#pragma unroll
            for (int jj = 0; jj < 2; ++jj) {
                const int j24 = 2 * p + jj;
                const float2* wrow =
                    reinterpret_cast<const float2*>(&wsm[(j24 * 32 + lane) * 26]);
                float2 wv[12];
#pragma unroll
                for (int op = 0; op < 12; ++op) wv[op] = wrow[op];
#pragma unroll
                for (int bi = 0; bi < 4; ++bi) {
                    float hv = hbuf[p & 1][jj * 4 + bi];
                    unsigned long long hv2 = pack2(hv, hv);
#pragma unroll
                    for (int op = 0; op < 12; ++op)
                        acc[bi][op] = ffma2(pack2(wv[op].x, wv[op].y), hv2, acc[bi][op]);
                }
            }
        }
    }

    // butterfly reduce over lanes (packed f32x2 adds)
#pragma unroll
    for (int bi = 0; bi < 4; ++bi)
#pragma unroll
        for (int op = 0; op < 12; ++op) {
            unsigned long long v = acc[bi][op];
#pragma unroll
            for (int m = 16; m > 0; m >>= 1) {
                double o = __shfl_xor_sync(0xffffffffu, __longlong_as_double((long long)v), m);
                v = addf2(v, (unsigned long long)__double_as_longlong(o));
            }
            acc[bi][op] = v;
        }

    // lane op (0..11) writes output pair (2op, 2op+1) for each of its 4 b's
#pragma unroll
    for (int bi = 0; bi < 4; ++bi) {
#pragma unroll
        for (int op = 0; op < 12; ++op) {
            if (lane == op) {
                float a0, a1;
                unpack2(acc[bi][op], a0, a1);
                float2 o2;
                o2.x = a0 + pb[2 * op];
                o2.y = a1 + pb[2 * op + 1];
                *reinterpret_cast<float2*>(&out[(size_t)((k * BBATCH + b0 + bi) * OO) + 2 * op]) = o2;
            }
        }
    }
}

// ============================================================================
extern "C" void kernel_launch(void* const* d_in, const int* in_sizes, int n_in,
                              void* d_out, int out_size) {
    const float* x   = (const float*)d_in[0];   // [32][64][128][128]
    const int*   pos = (const int*)  d_in[1];   // [1000][32][12][2]
    const float* cw  = (const float*)d_in[2];   // [64][64][3][3]
    const float* cb  = (const float*)d_in[3];   // [64]
    const float* pw  = (const float*)d_in[4];   // [24][768]
    const float* pb  = (const float*)d_in[5];   // [24]
    float* out = (float*)d_out;                 // [1000][32][24]

    cudaFuncSetAttribute(conv_tc_kernel, cudaFuncAttributeMaxDynamicSharedMemorySize, SM_TOT);

    wprep_kernel<<<(CC * CC * 9 + 255) / 256, 256>>>(cw);
    conv_tc_kernel<<<dim3(HW / 2, BBATCH), 256, SM_TOT>>>(x, cb);
    gather_fc_kernel<<<KK, 256>>>(pos, pw, pb, out);
}